// round 8
// baseline (speedup 1.0000x reference)
#include <cuda_runtime.h>
#include <cstdint>

// x (8, 3, 65536) f32 -> out (8, 3, 512) f32, farthest point sampling.
#define BATCHES 8
#define NPTS    65536
#define MOUT    512
#define CLUSTER 8                         // CTAs per batch (one cluster)
#define TPB     256
#define TPBATCH (CLUSTER * TPB)           // 2048 threads per batch
#define PPT     (NPTS / TPBATCH)          // 32 points per thread (register-resident)
#define PAIRS   (PPT / 2)                 // 16 packed f32x2 pairs

typedef unsigned long long u64;
typedef unsigned int u32;

// ---- cluster helpers (ALL mapa must be asm volatile: non-volatile mapa with
//      rank=lane gets if-converted to lanes>=8 -> invalid rank -> IMA) ----
__device__ __forceinline__ u32 cluster_rank() {
    u32 r; asm("mov.u32 %0, %%cluster_ctarank;" : "=r"(r)); return r;
}
__device__ __forceinline__ u32 smem_u32(const void* p) {
    return (u32)__cvta_generic_to_shared(p);
}
__device__ __forceinline__ void cluster_sync_all() {
    asm volatile("barrier.cluster.arrive.aligned;" ::: "memory");
    asm volatile("barrier.cluster.wait.aligned;"   ::: "memory");
}
// ---- packed f32x2 math (per-lane IEEE .rn, bit-identical to scalar) ----
__device__ __forceinline__ u64 f2pack(float lo, float hi) {
    u64 r; asm("mov.b64 %0, {%1, %2};" : "=l"(r) : "f"(lo), "f"(hi)); return r;
}
__device__ __forceinline__ void f2unpack(float& lo, float& hi, u64 v) {
    asm("mov.b64 {%0, %1}, %2;" : "=f"(lo), "=f"(hi) : "l"(v));
}
__device__ __forceinline__ u64 f2add(u64 a, u64 b) {
    u64 r; asm("add.rn.f32x2 %0, %1, %2;" : "=l"(r) : "l"(a), "l"(b)); return r;
}
__device__ __forceinline__ u64 f2mul(u64 a, u64 b) {
    u64 r; asm("mul.rn.f32x2 %0, %1, %2;" : "=l"(r) : "l"(a), "l"(b)); return r;
}

// Mailbox slot (16B): [0..7]=key u64, [8..11]=tag u32, [12..15]=pad
__global__ void __launch_bounds__(TPB, 1) __cluster_dims__(CLUSTER, 1, 1)
fps_kernel(const float* __restrict__ x, float* __restrict__ out)
{
    __shared__ u64 s_wkey[TPB / 32];                     // per-warp winners
    __shared__ __align__(16) u64 s_slot[2][CLUSTER][2];  // [parity][src_rank][key,tag]

    const u32 rank = cluster_rank();
    const int b    = blockIdx.x / CLUSTER;
    const int tid  = threadIdx.x;
    const int lane = tid & 31;
    const int warp = tid >> 5;
    const int tcl  = (int)rank * TPB + tid;              // 0..2047 within batch

    const float* __restrict__ xb = x + (size_t)b * 3 * NPTS;
    float* __restrict__ ob       = out + (size_t)b * 3 * MOUT;

    // Register-resident points (packed pairs) + running min distance
    u64 px2[PAIRS], py2[PAIRS], pz2[PAIRS];
    float dist[PPT];
#pragma unroll
    for (int i = 0; i < PAIRS; i++) {
        int k0 = 2 * i, k1 = 2 * i + 1;
        int g0 = k0 * TPBATCH + tcl, g1 = k1 * TPBATCH + tcl;   // coalesced
        px2[i] = f2pack(__ldg(xb + g0),            __ldg(xb + g1));
        py2[i] = f2pack(__ldg(xb + NPTS + g0),     __ldg(xb + NPTS + g1));
        pz2[i] = f2pack(__ldg(xb + 2 * NPTS + g0), __ldg(xb + 2 * NPTS + g1));
        dist[k0] = INFINITY;
        dist[k1] = INFINITY;
    }

    // init mailbox tags to 0 (tags used are j = 1..511)
    if (tid < CLUSTER * 2) {
        s_slot[tid & 1][tid >> 1][1] = 0ULL;
    }

    // First centroid is point 0 (standard PointNet++ convention)
    float cx = __ldg(xb);
    float cy = __ldg(xb + NPTS);
    float cz = __ldg(xb + 2 * NPTS);
    if (rank == 0 && tid == 0) {
        ob[0]        = cx;
        ob[MOUT]     = cy;
        ob[2 * MOUT] = cz;
    }

    __syncthreads();
    cluster_sync_all();   // all tags zeroed everywhere before any mailbox store

    // address of the tag this warp polls: slot of src_rank == warp
    const u32 tag0 = smem_u32(&s_slot[0][warp][1]);
    const u32 tag1 = smem_u32(&s_slot[1][warp][1]);

    for (int j = 1; j < MOUT; j++) {
        // ---- pass 1: packed distance update. Per-lane .rn arithmetic, same
        //      order as reference: (dx*dx + dy*dy) + dz*dz. Track max only. ----
        u64 ncx = f2pack(-cx, -cx);
        u64 ncy = f2pack(-cy, -cy);
        u64 ncz = f2pack(-cz, -cz);
        float best = -1.0f;
#pragma unroll
        for (int i = 0; i < PAIRS; i++) {
            u64 dx = f2add(px2[i], ncx);
            u64 dy = f2add(py2[i], ncy);
            u64 dz = f2add(pz2[i], ncz);
            u64 s  = f2add(f2mul(dx, dx), f2mul(dy, dy));
            u64 dd = f2add(s, f2mul(dz, dz));
            float e0, e1;
            f2unpack(e0, e1, dd);
            float n0 = fminf(dist[2 * i],     e0);
            float n1 = fminf(dist[2 * i + 1], e1);
            dist[2 * i]     = n0;
            dist[2 * i + 1] = n1;
            best = fmaxf(best, fmaxf(n0, n1));
        }

        // ---- pass 2: min k among dist[k]==best (first-occurrence argmax) ----
        int kb = 0x7FFFFFFF;
#pragma unroll
        for (int k = 0; k < PPT; k++) {
            if (dist[k] == best) kb = min(kb, k);
        }
        int bidx = kb * TPBATCH + tcl;

        // Packed key: (dist bits << 32) | ~idx  -> max picks largest dist,
        // ties resolved to the LOWEST index (jnp.argmax first-occurrence).
        u64 key = ((u64)__float_as_uint(best) << 32) |
                  (u64)(u32)(~(u32)bidx);

        // ---- warp reduce (proven shuffle chain) ----
#pragma unroll
        for (int off = 16; off > 0; off >>= 1) {
            u64 k2 = __shfl_down_sync(0xFFFFFFFFu, key, off);
            if (k2 > key) key = k2;
        }
        if (lane == 0) s_wkey[warp] = key;
        __syncthreads();

        // ---- block reduce: warp 0 butterfly so lanes 0..7 all hold the block
        //      winner; lane r publishes {key, tag=j} into rank r's mailbox ----
        if (warp == 0) {
            u64 bk = s_wkey[lane & 7];
#pragma unroll
            for (int off = 4; off > 0; off >>= 1) {
                u64 k2 = __shfl_xor_sync(0xFFFFFFFFu, bk, off);
                if (k2 > bk) bk = k2;
            }
            if (lane < CLUSTER) {
                u32 laddr = smem_u32(&s_slot[j & 1][rank][0]);
                u32 dst;
                asm volatile("mapa.shared::cluster.u32 %0, %1, %2;"
                             : "=r"(dst) : "r"(laddr), "r"((u32)lane));
                asm volatile("st.shared::cluster.u64 [%0], %1;"
                             :: "r"(dst), "l"(bk) : "memory");
                // release orders the key store before the tag store at the
                // destination CTA.
                asm volatile("st.release.cluster.shared::cluster.u32 [%0], %1;"
                             :: "r"(dst + 8), "r"((u32)j) : "memory");
            }
        }

        // ---- poll: warp w spins on tag w only (broadcast LDS, one per pass);
        //      __syncthreads then certifies all 8 tags == j block-wide ----
        {
            const u32 taddr = (j & 1) ? tag1 : tag0;
            u32 t;
            do {
                asm volatile("ld.volatile.shared.u32 %0, [%1];"
                             : "=r"(t) : "r"(taddr) : "memory");
            } while (t != (u32)j);
        }
        __syncthreads();

        // ---- select global winner from 8 local candidates ----
        const u64* cand = &s_slot[j & 1][0][0];
        u64 wk = cand[0];
#pragma unroll
        for (int r = 1; r < CLUSTER; r++) {
            u64 c = cand[r * 2];
            if (c > wk) wk = c;
        }
        int widx = (int)(~(u32)wk);

        // ---- fetch winning centroid coords (no cluster fence in the loop ->
        //      x lines persist in L1; hits after warmup) ----
        cx = __ldg(xb + widx);
        cy = __ldg(xb + NPTS + widx);
        cz = __ldg(xb + 2 * NPTS + widx);

        if (rank == 0 && tid == 0) {
            ob[j]            = cx;
            ob[MOUT + j]     = cy;
            ob[2 * MOUT + j] = cz;
        }
    }

    // No CTA may exit (deallocating its SMEM) while peers' remote stores
    // targeting it could still be in flight.
    cluster_sync_all();
}

extern "C" void kernel_launch(void* const* d_in, const int* in_sizes, int n_in,
                              void* d_out, int out_size)
{
    const float* x = (const float*)d_in[0];
    float* out     = (float*)d_out;
    fps_kernel<<<BATCHES * CLUSTER, TPB>>>(x, out);
}

// round 10
// speedup vs baseline: 1.0764x; 1.0764x over previous
#include <cuda_runtime.h>
#include <cstdint>

// x (8, 3, 65536) f32 -> out (8, 3, 512) f32, farthest point sampling.
#define BATCHES 8
#define NPTS    65536
#define MOUT    512
#define CLUSTER 8                         // CTAs per batch (one cluster)
#define TPB     256
#define TPBATCH (CLUSTER * TPB)           // 2048 threads per batch
#define PPT     (NPTS / TPBATCH)          // 32 points per thread (register-resident)
#define PAIRS   (PPT / 2)                 // 16 packed f32x2 pairs

typedef unsigned long long u64;
typedef unsigned int u32;

// ---- cluster helpers ----
__device__ __forceinline__ u32 cluster_rank() {
    u32 r; asm("mov.u32 %0, %%cluster_ctarank;" : "=r"(r)); return r;
}
__device__ __forceinline__ u32 smem_u32(const void* p) {
    return (u32)__cvta_generic_to_shared(p);
}
__device__ __forceinline__ void cluster_sync_all() {
    asm volatile("barrier.cluster.arrive.aligned;" ::: "memory");
    asm volatile("barrier.cluster.wait.aligned;"   ::: "memory");
}
// ---- packed f32x2 math (per-lane IEEE .rn, bit-identical to scalar) ----
__device__ __forceinline__ u64 f2pack(float lo, float hi) {
    u64 r; asm("mov.b64 %0, {%1, %2};" : "=l"(r) : "f"(lo), "f"(hi)); return r;
}
__device__ __forceinline__ void f2unpack(float& lo, float& hi, u64 v) {
    asm("mov.b64 {%0, %1}, %2;" : "=f"(lo), "=f"(hi) : "l"(v));
}
__device__ __forceinline__ u64 f2add(u64 a, u64 b) {
    u64 r; asm("add.rn.f32x2 %0, %1, %2;" : "=l"(r) : "l"(a), "l"(b)); return r;
}
__device__ __forceinline__ u64 f2mul(u64 a, u64 b) {
    u64 r; asm("mul.rn.f32x2 %0, %1, %2;" : "=l"(r) : "l"(a), "l"(b)); return r;
}

// Slots (all STATIC smem; dynamic smem is implicated in every IMA so far):
//   s_wslot[warp]: [0]=key, [1]=(cx,cy), [2]=(cz,0)   -- per-warp winner msg
//   s_slot[parity][src_rank]: same layout             -- cluster candidates
__global__ void __launch_bounds__(TPB, 1) __cluster_dims__(CLUSTER, 1, 1)
fps_kernel(const float* __restrict__ x, float* __restrict__ out)
{
    __shared__ __align__(16) u64 s_wslot[TPB / 32][4];
    __shared__ __align__(16) u64 s_slot[2][CLUSTER][4];

    const u32 rank = cluster_rank();
    const int b    = blockIdx.x / CLUSTER;
    const int tid  = threadIdx.x;
    const int lane = tid & 31;
    const int warp = tid >> 5;
    const int tcl  = (int)rank * TPB + tid;       // 0..2047 within batch

    const float* __restrict__ xb = x + (size_t)b * 3 * NPTS;
    float* __restrict__ ob       = out + (size_t)b * 3 * MOUT;

    // Register-resident points (packed pairs) + running min distance
    u64 px2[PAIRS], py2[PAIRS], pz2[PAIRS];
    float dist[PPT];
#pragma unroll
    for (int i = 0; i < PAIRS; i++) {
        int k0 = 2 * i, k1 = 2 * i + 1;
        int g0 = k0 * TPBATCH + tcl, g1 = k1 * TPBATCH + tcl;   // coalesced
        px2[i] = f2pack(__ldg(xb + g0),            __ldg(xb + g1));
        py2[i] = f2pack(__ldg(xb + NPTS + g0),     __ldg(xb + NPTS + g1));
        pz2[i] = f2pack(__ldg(xb + 2 * NPTS + g0), __ldg(xb + 2 * NPTS + g1));
        dist[k0] = INFINITY;
        dist[k1] = INFINITY;
    }

    // First centroid is point 0 (standard PointNet++ convention)
    float cx = __ldg(xb);
    float cy = __ldg(xb + NPTS);
    float cz = __ldg(xb + 2 * NPTS);
    if (rank == 0 && tid == 0) {
        ob[0]        = cx;
        ob[MOUT]     = cy;
        ob[2 * MOUT] = cz;
    }

    for (int j = 1; j < MOUT; j++) {
        // ---- pass 1: packed distance update. Per-lane .rn arithmetic, same
        //      order as reference: (dx*dx + dy*dy) + dz*dz. Track max only. ----
        u64 ncx = f2pack(-cx, -cx);
        u64 ncy = f2pack(-cy, -cy);
        u64 ncz = f2pack(-cz, -cz);
        float best = -1.0f;
#pragma unroll
        for (int i = 0; i < PAIRS; i++) {
            u64 dx = f2add(px2[i], ncx);
            u64 dy = f2add(py2[i], ncy);
            u64 dz = f2add(pz2[i], ncz);
            u64 s  = f2add(f2mul(dx, dx), f2mul(dy, dy));
            u64 dd = f2add(s, f2mul(dz, dz));
            float e0, e1;
            f2unpack(e0, e1, dd);
            float n0 = fminf(dist[2 * i],     e0);
            float n1 = fminf(dist[2 * i + 1], e1);
            dist[2 * i]     = n0;
            dist[2 * i + 1] = n1;
            best = fmaxf(best, fmaxf(n0, n1));
        }

        // ---- pass 2: min k among dist[k]==best (first-occurrence argmax) ----
        int kb = 0x7FFFFFFF;
#pragma unroll
        for (int k = 0; k < PPT; k++) {
            if (dist[k] == best) kb = min(kb, k);
        }
        u32 bidx = (u32)(kb * TPBATCH + tcl);

        // ---- warp reduce via REDUX (R6-proven numerics): max dist bits, then
        //      min index among ties (sq dists >= 0 so u32 order == float order;
        //      min idx == jnp.argmax first-occurrence) ----
        u32 dbits = __float_as_uint(best);
        u32 wmax  = __reduce_max_sync(0xFFFFFFFFu, dbits);
        u32 cnd   = (dbits == wmax) ? bidx : 0xFFFFFFFFu;
        u32 wmin  = __reduce_min_sync(0xFFFFFFFFu, cnd);

        // ---- the unique warp-winner thread ships key + ITS OWN candidate's
        //      coords (register select on kb, fully unrolled -> no spill) ----
        if (dbits == wmax && bidx == wmin) {
            u64 sx = px2[0], sy = py2[0], sz = pz2[0];
            int pi = kb >> 1;
#pragma unroll
            for (int i = 1; i < PAIRS; i++) {
                if (pi == i) { sx = px2[i]; sy = py2[i]; sz = pz2[i]; }
            }
            float x0, x1, y0, y1, z0, z1;
            f2unpack(x0, x1, sx);
            f2unpack(y0, y1, sy);
            f2unpack(z0, z1, sz);
            float wx = (kb & 1) ? x1 : x0;
            float wy = (kb & 1) ? y1 : y0;
            float wz = (kb & 1) ? z1 : z0;
            s_wslot[warp][0] = ((u64)wmax << 32) | (u32)~wmin;   // key
            s_wslot[warp][1] = f2pack(wx, wy);
            s_wslot[warp][2] = f2pack(wz, 0.0f);
        }
        __syncthreads();

        // ---- block reduce (warp 0): REDUX over 8 per-warp keys, find winning
        //      warp, lanes 0..7 fan {key, coords} out to all 8 ranks ----
        if (warp == 0) {
            u64 k  = s_wslot[lane & 7][0];      // lanes 8-31 read duplicates
            u32 h  = (u32)(k >> 32);
            u32 lo = (u32)k;
            u32 hmax = __reduce_max_sync(0xFFFFFFFFu, h);
            u32 lsel = (h == hmax) ? lo : 0u;   // max(~idx) == min idx
            u32 lmax = __reduce_max_sync(0xFFFFFFFFu, lsel);
            u64 bk   = ((u64)hmax << 32) | lmax;
            u32 wl   = (k == bk) ? (u32)(lane & 7) : 32u;
            u32 wwarp = __reduce_min_sync(0xFFFFFFFFu, wl);
            if (lane < CLUSTER) {
                u64 cxy = s_wslot[wwarp][1];    // broadcast LDS
                u64 cz_ = s_wslot[wwarp][2];
                u32 laddr = smem_u32(&s_slot[j & 1][rank][0]);
                u32 dst;
                asm volatile("mapa.shared::cluster.u32 %0, %1, %2;"
                             : "=r"(dst) : "r"(laddr), "r"((u32)lane));
                asm volatile("st.shared::cluster.u64 [%0], %1;"
                             :: "r"(dst), "l"(bk) : "memory");
                asm volatile("st.shared::cluster.u64 [%0], %1;"
                             :: "r"(dst + 8), "l"(cxy) : "memory");
                asm volatile("st.shared::cluster.u64 [%0], %1;"
                             :: "r"(dst + 16), "l"(cz_) : "memory");
            }
        }

        // ---- cluster barrier: arrive(release)/wait(acquire) orders the remote
        //      stores against the local reads below (R1/R5-proven) ----
        cluster_sync_all();

        // ---- select global winner from 8 local slots -> coords directly ----
        {
            const u64* slots = &s_slot[j & 1][0][0];
            u64 wk = slots[0]; int ws = 0;
#pragma unroll
            for (int r = 1; r < CLUSTER; r++) {
                u64 c = slots[r * 4];
                if (c > wk) { wk = c; ws = r; }
            }
            float dummy;
            f2unpack(cx, cy, slots[ws * 4 + 1]);
            f2unpack(cz, dummy, slots[ws * 4 + 2]);
        }

        if (rank == 0 && tid == 0) {
            ob[j]            = cx;
            ob[MOUT + j]     = cy;
            ob[2 * MOUT + j] = cz;
        }
    }
}

extern "C" void kernel_launch(void* const* d_in, const int* in_sizes, int n_in,
                              void* d_out, int out_size)
{
    const float* x = (const float*)d_in[0];
    float* out     = (float*)d_out;
    fps_kernel<<<BATCHES * CLUSTER, TPB>>>(x, out);
}